// round 1
// baseline (speedup 1.0000x reference)
#include <cuda_runtime.h>
#include <math.h>

#define BB 2
#define SS 2048
#define HH 12
#define DD 64

#define TI 64
#define TJ 64
#define PAD 65

// scratch for rotated q/k/v in [b,h,s,d] layout
__device__ float g_q[BB*HH*SS*DD];
__device__ float g_k[BB*HH*SS*DD];
__device__ float g_v[BB*HH*SS*DD];

// ---------------------------------------------------------------------------
// Kernel 1: rotary embedding + transpose (b,s,3,h,d) -> 3x (b,h,s,d)
// rotate_half: out[d<32]  = x1*cos - x2*sin
//              out[d>=32] = x2*cos + x1*sin
// cos/sin shape [1,S,3,1,D]; t==2 slice is identity (cos=1,sin=0) in the data.
// ---------------------------------------------------------------------------
__global__ void rotary_kernel(const float* __restrict__ qkv,
                              const float* __restrict__ cosb,
                              const float* __restrict__ sinb) {
    int idx = blockIdx.x * blockDim.x + threadIdx.x;
    const int total = BB * SS * 3 * HH * (DD / 2);
    if (idx >= total) return;
    int d2  = idx & 31; int rest = idx >> 5;
    int h   = rest % HH; rest /= HH;
    int t   = rest % 3;  rest /= 3;
    int s   = rest % SS; int b = rest / SS;

    size_t qoff = ((((size_t)b * SS + s) * 3 + t) * HH + h) * DD + d2;
    float x1 = qkv[qoff];
    float x2 = qkv[qoff + 32];

    int coff = (s * 3 + t) * DD + d2;   // cos[d2] == cos[d2+32] (concat(freqs,freqs))
    float c  = cosb[coff];
    float sn = sinb[coff];

    float o1 = x1 * c - x2 * sn;
    float o2 = x2 * c + x1 * sn;

    float* dst = (t == 0) ? g_q : ((t == 1) ? g_k : g_v);
    size_t doff = (((size_t)b * HH + h) * SS + s) * DD + d2;
    dst[doff]      = o1;
    dst[doff + 32] = o2;
}

// ---------------------------------------------------------------------------
// Kernel 2: flash-style attention with logits streamed to gmem.
// Grid: (S/TI, B*H). Block: 256 threads = 16x16, each thread owns a 4x4 tile.
// Online softmax per row; masked logits written exactly as -1e10f.
// Fully-masked rows (i >= seqlen) degrade to uniform softmax = mean(v),
// matching the reference.
// ---------------------------------------------------------------------------
__global__ void attn_kernel(const int* __restrict__ seqlens,
                            float* __restrict__ out_x,
                            float* __restrict__ out_logits) {
    extern __shared__ float smem[];
    float* sQ = smem;                 // TI x PAD
    float* sK = sQ + TI * PAD;        // TJ x PAD
    float* sV = sK + TJ * PAD;        // TJ x PAD
    float* sP = sV + TJ * PAD;        // TI x PAD
    __shared__ float sM[TI], sL[TI], sFac[TI];

    const int bh  = blockIdx.y;
    const int b   = bh / HH;
    const int i0  = blockIdx.x * TI;
    const int tid = threadIdx.x;
    const int ty  = tid >> 4;   // 0..15
    const int tx  = tid & 15;   // 0..15
    const int seqlen = seqlens[b];

    const float* Qb = g_q + (size_t)bh * SS * DD;
    const float* Kb = g_k + (size_t)bh * SS * DD;
    const float* Vb = g_v + (size_t)bh * SS * DD;

    // load Q tile (coalesced float4 reads, padded smem writes)
    {
        const float4* src = (const float4*)(Qb + (size_t)i0 * DD);
        #pragma unroll
        for (int k = tid; k < TI * DD / 4; k += 256) {
            float4 v = src[k];
            int r = k >> 4;            // 16 float4 per row
            int c = (k & 15) << 2;
            float* p = sQ + r * PAD + c;
            p[0] = v.x; p[1] = v.y; p[2] = v.z; p[3] = v.w;
        }
    }
    if (tid < TI) { sM[tid] = -INFINITY; sL[tid] = 0.f; }

    float acc[4][4];
    #pragma unroll
    for (int ii = 0; ii < 4; ii++)
        #pragma unroll
        for (int dd = 0; dd < 4; dd++) acc[ii][dd] = 0.f;

    int  irow[4]; bool ivalid[4];
    #pragma unroll
    for (int ii = 0; ii < 4; ii++) {
        irow[ii]   = i0 + ty * 4 + ii;
        ivalid[ii] = irow[ii] < seqlen;
    }

    for (int j0 = 0; j0 < SS; j0 += TJ) {
        __syncthreads();  // prior iteration's PV done before tile overwrite; Q ready on iter 0
        {
            const float4* ks = (const float4*)(Kb + (size_t)j0 * DD);
            const float4* vs = (const float4*)(Vb + (size_t)j0 * DD);
            #pragma unroll
            for (int k = tid; k < TJ * DD / 4; k += 256) {
                int r = k >> 4;
                int c = (k & 15) << 2;
                float4 v = ks[k];
                float* p = sK + r * PAD + c;
                p[0] = v.x; p[1] = v.y; p[2] = v.z; p[3] = v.w;
                v = vs[k];
                p = sV + r * PAD + c;
                p[0] = v.x; p[1] = v.y; p[2] = v.z; p[3] = v.w;
            }
        }
        __syncthreads();

        // QK^T: 64x64x64 tile gemm, 4x4 register tile per thread
        float sreg[4][4];
        #pragma unroll
        for (int ii = 0; ii < 4; ii++)
            #pragma unroll
            for (int jj = 0; jj < 4; jj++) sreg[ii][jj] = 0.f;

        #pragma unroll 8
        for (int d = 0; d < DD; d++) {
            float qf[4], kf[4];
            #pragma unroll
            for (int ii = 0; ii < 4; ii++) qf[ii] = sQ[(ty * 4 + ii) * PAD + d];
            #pragma unroll
            for (int jj = 0; jj < 4; jj++) kf[jj] = sK[(tx * 4 + jj) * PAD + d];
            #pragma unroll
            for (int ii = 0; ii < 4; ii++)
                #pragma unroll
                for (int jj = 0; jj < 4; jj++)
                    sreg[ii][jj] = fmaf(qf[ii], kf[jj], sreg[ii][jj]);
        }

        // scale + mask; stream logits to gmem (float4) and stage into sP
        const int jbase = j0 + tx * 4;
        #pragma unroll
        for (int ii = 0; ii < 4; ii++) {
            float4 o;
            float* ov = &o.x;
            #pragma unroll
            for (int jj = 0; jj < 4; jj++) {
                float v = (ivalid[ii] && (jbase + jj) < seqlen)
                            ? sreg[ii][jj] * 0.125f : -1e10f;
                ov[jj] = v;
                sP[(ty * 4 + ii) * PAD + (tx * 4 + jj)] = v;
            }
            *(float4*)(out_logits + ((size_t)bh * SS + irow[ii]) * SS + jbase) = o;
        }
        __syncthreads();

        // online softmax update: 4 threads per row, 16 cols each
        {
            int r = tid >> 2, q = tid & 3;
            float* row = sP + r * PAD + q * 16;
            float tmax = row[0];
            #pragma unroll
            for (int c = 1; c < 16; c++) tmax = fmaxf(tmax, row[c]);
            tmax = fmaxf(tmax, __shfl_xor_sync(0xffffffffu, tmax, 1));
            tmax = fmaxf(tmax, __shfl_xor_sync(0xffffffffu, tmax, 2));
            float mold = sM[r];
            float mnew = fmaxf(mold, tmax);
            float psum = 0.f;
            #pragma unroll
            for (int c = 0; c < 16; c++) {
                float p = __expf(row[c] - mnew);
                row[c] = p;
                psum += p;
            }
            psum += __shfl_xor_sync(0xffffffffu, psum, 1);
            psum += __shfl_xor_sync(0xffffffffu, psum, 2);
            if (q == 0) {
                float fac = __expf(mold - mnew);  // mold=-inf -> 0 on iter 0
                sL[r]   = sL[r] * fac + psum;
                sM[r]   = mnew;
                sFac[r] = fac;
            }
        }
        __syncthreads();

        // rescale accumulator and do P*V (64x64x64 tile gemm)
        #pragma unroll
        for (int ii = 0; ii < 4; ii++) {
            float f = sFac[ty * 4 + ii];
            #pragma unroll
            for (int dd = 0; dd < 4; dd++) acc[ii][dd] *= f;
        }
        #pragma unroll 8
        for (int j = 0; j < TJ; j++) {
            float pv[4], vv[4];
            #pragma unroll
            for (int ii = 0; ii < 4; ii++) pv[ii] = sP[(ty * 4 + ii) * PAD + j];
            #pragma unroll
            for (int dd = 0; dd < 4; dd++) vv[dd] = sV[j * PAD + tx * 4 + dd];
            #pragma unroll
            for (int ii = 0; ii < 4; ii++)
                #pragma unroll
                for (int dd = 0; dd < 4; dd++)
                    acc[ii][dd] = fmaf(pv[ii], vv[dd], acc[ii][dd]);
        }
    }

    // epilogue: x = acc / l
    #pragma unroll
    for (int ii = 0; ii < 4; ii++) {
        float linv = 1.f / sL[ty * 4 + ii];
        float4 o = make_float4(acc[ii][0] * linv, acc[ii][1] * linv,
                               acc[ii][2] * linv, acc[ii][3] * linv);
        *(float4*)(out_x + ((size_t)bh * SS + irow[ii]) * DD + tx * 4) = o;
    }
}

extern "C" void kernel_launch(void* const* d_in, const int* in_sizes, int n_in,
                              void* d_out, int out_size) {
    const float* qkv     = (const float*)d_in[0];
    const float* cosb    = (const float*)d_in[1];
    const float* sinb    = (const float*)d_in[2];
    const int*   seqlens = (const int*)d_in[3];

    float* out        = (float*)d_out;
    float* out_x      = out;                                  // [B,H,S,D]
    float* out_logits = out + (size_t)BB * HH * SS * DD;      // [B,H,S,S]

    const int total = BB * SS * 3 * HH * (DD / 2);
    rotary_kernel<<<(total + 255) / 256, 256>>>(qkv, cosb, sinb);

    const int smem_bytes = 4 * TI * PAD * (int)sizeof(float); // 66560 B
    cudaFuncSetAttribute(attn_kernel,
                         cudaFuncAttributeMaxDynamicSharedMemorySize, smem_bytes);
    dim3 grid(SS / TI, BB * HH);
    attn_kernel<<<grid, 256, smem_bytes>>>(seqlens, out_x, out_logits);
}

// round 3
// speedup vs baseline: 2.3155x; 2.3155x over previous
#include <cuda_runtime.h>
#include <cuda_bf16.h>
#include <math.h>
#include <stdint.h>

#define BB 2
#define SS 2048
#define HH 12
#define DD 64
#define BH (BB*HH)

#define TI 128
#define TJ 64
#define NJT (SS/TJ)
#define NTHREADS 256

#define NELEM (BB*HH*SS*DD)
// rotated bf16 hi/lo operands
__device__ __nv_bfloat16 g_qh[NELEM], g_ql[NELEM];   // [bh][s][d]
__device__ __nv_bfloat16 g_kh[NELEM], g_kl[NELEM];   // [bh][s][d]
__device__ __nv_bfloat16 g_vth[NELEM], g_vtl[NELEM]; // [bh][d][s] (transposed)

// ---------------------------------------------------------------------------
__device__ __forceinline__ void mma_bf16(float (&c)[4], const uint32_t* a,
                                         uint32_t b0, uint32_t b1) {
    asm volatile(
        "mma.sync.aligned.m16n8k16.row.col.f32.bf16.bf16.f32 "
        "{%0,%1,%2,%3}, {%4,%5,%6,%7}, {%8,%9}, {%0,%1,%2,%3};\n"
        : "+f"(c[0]), "+f"(c[1]), "+f"(c[2]), "+f"(c[3])
        : "r"(a[0]), "r"(a[1]), "r"(a[2]), "r"(a[3]), "r"(b0), "r"(b1));
}

__device__ __forceinline__ uint32_t pack_bf16x2(float lo, float hi) {
    __nv_bfloat162 t = __floats2bfloat162_rn(lo, hi);  // x=lo(low half), y=hi
    return *(uint32_t*)&t;
}

// ---------------------------------------------------------------------------
// rotary for q,k -> bf16 hi/lo in [bh][s][d]
// ---------------------------------------------------------------------------
__global__ void rotary_qk_kernel(const float* __restrict__ qkv,
                                 const float* __restrict__ cosb,
                                 const float* __restrict__ sinb) {
    int idx = blockIdx.x * blockDim.x + threadIdx.x;
    const int total = BB * SS * 2 * HH * 32;
    if (idx >= total) return;
    int d2 = idx & 31; int rest = idx >> 5;
    int h = rest % HH; rest /= HH;
    int t = rest & 1;  rest >>= 1;
    int s = rest % SS; int b = rest / SS;

    size_t qoff = ((((size_t)b * SS + s) * 3 + t) * HH + h) * DD + d2;
    float x1 = qkv[qoff];
    float x2 = qkv[qoff + 32];
    int coff = (s * 3 + t) * DD + d2;
    float c = cosb[coff], sn = sinb[coff];
    float o1 = x1 * c - x2 * sn;
    float o2 = x2 * c + x1 * sn;

    __nv_bfloat16 h1 = __float2bfloat16_rn(o1);
    __nv_bfloat16 l1 = __float2bfloat16_rn(o1 - __bfloat162float(h1));
    __nv_bfloat16 h2 = __float2bfloat16_rn(o2);
    __nv_bfloat16 l2 = __float2bfloat16_rn(o2 - __bfloat162float(h2));

    __nv_bfloat16* dh = (t == 0) ? g_qh : g_kh;
    __nv_bfloat16* dl = (t == 0) ? g_ql : g_kl;
    size_t doff = (((size_t)b * HH + h) * SS + s) * DD + d2;
    dh[doff] = h1; dh[doff + 32] = h2;
    dl[doff] = l1; dl[doff + 32] = l2;
}

// ---------------------------------------------------------------------------
// v: rotary (identity slice) + transpose -> [bh][d][s] bf16 hi/lo
// grid (SS/64, BH), 256 threads; 64s x 64d tile through smem
// ---------------------------------------------------------------------------
__global__ void vtrans_kernel(const float* __restrict__ qkv,
                              const float* __restrict__ cosb,
                              const float* __restrict__ sinb) {
    __shared__ __nv_bfloat16 sTh[64 * 72];
    __shared__ __nv_bfloat16 sTl[64 * 72];
    const int bh = blockIdx.y;
    const int b = bh / HH, h = bh % HH;
    const int s0 = blockIdx.x * 64;
    const int tid = threadIdx.x;
    const int sl = tid >> 2;           // 0..63
    const int d2b = (tid & 3) * 8;     // 0,8,16,24
    const int s = s0 + sl;

    const float* base = qkv + (((size_t)(b * SS + s) * 3 + 2) * HH + h) * DD;
    const float* cb = cosb + (s * 3 + 2) * DD;
    const float* sb = sinb + (s * 3 + 2) * DD;
    #pragma unroll
    for (int i = 0; i < 8; i++) {
        int d = d2b + i;
        float x1 = base[d], x2 = base[d + 32];
        float c = cb[d], sn = sb[d];
        float o1 = x1 * c - x2 * sn;
        float o2 = x2 * c + x1 * sn;
        __nv_bfloat16 h1 = __float2bfloat16_rn(o1);
        __nv_bfloat16 l1 = __float2bfloat16_rn(o1 - __bfloat162float(h1));
        __nv_bfloat16 h2 = __float2bfloat16_rn(o2);
        __nv_bfloat16 l2 = __float2bfloat16_rn(o2 - __bfloat162float(h2));
        sTh[d * 72 + sl] = h1; sTh[(d + 32) * 72 + sl] = h2;
        sTl[d * 72 + sl] = l1; sTl[(d + 32) * 72 + sl] = l2;
    }
    __syncthreads();
    #pragma unroll
    for (int c = tid; c < 512; c += NTHREADS) {
        int r = c >> 3, co = (c & 7) * 8;
        size_t dst = ((size_t)bh * DD + r) * SS + s0 + co;
        *(uint4*)(g_vth + dst) = *(const uint4*)(sTh + r * 72 + co);
        *(uint4*)(g_vtl + dst) = *(const uint4*)(sTl + r * 72 + co);
    }
}

// ---------------------------------------------------------------------------
// single-pass flash attention with mma.sync bf16 hi/lo split
// grid (SS/TI, BH), 256 threads (8 warps x 16 rows)
// ---------------------------------------------------------------------------
__global__ void __launch_bounds__(NTHREADS, 1)
attn_kernel(const int* __restrict__ seqlens,
            float* __restrict__ out_x,
            float* __restrict__ out_logits) {
    __shared__ __align__(16) __nv_bfloat16 sKh[64 * 72];
    __shared__ __align__(16) __nv_bfloat16 sKl[64 * 72];
    __shared__ __align__(16) __nv_bfloat16 sVh[64 * 72];
    __shared__ __align__(16) __nv_bfloat16 sVl[64 * 72];

    const int tid = threadIdx.x;
    const int wid = tid >> 5;
    const int lane = tid & 31;
    const int lq = lane >> 2;     // 0..7
    const int lr = lane & 3;      // 0..3

    const int bh = blockIdx.y;
    const int b = bh / HH;
    const int i0 = blockIdx.x * TI;
    const int seqlen = seqlens[b];
    const size_t bh_off = (size_t)bh * SS * DD;

    // persistent Q fragments (hi/lo)
    uint32_t aQh[16], aQl[16];
    {
        const __nv_bfloat16* q0 = g_qh + bh_off + (size_t)(i0 + wid * 16 + lq) * DD + 2 * lr;
        const __nv_bfloat16* q1 = g_ql + bh_off + (size_t)(i0 + wid * 16 + lq) * DD + 2 * lr;
        #pragma unroll
        for (int kt = 0; kt < 4; kt++) {
            aQh[kt*4+0] = *(const uint32_t*)(q0 + kt * 16);
            aQh[kt*4+1] = *(const uint32_t*)(q0 + 8 * DD + kt * 16);
            aQh[kt*4+2] = *(const uint32_t*)(q0 + kt * 16 + 8);
            aQh[kt*4+3] = *(const uint32_t*)(q0 + 8 * DD + kt * 16 + 8);
            aQl[kt*4+0] = *(const uint32_t*)(q1 + kt * 16);
            aQl[kt*4+1] = *(const uint32_t*)(q1 + 8 * DD + kt * 16);
            aQl[kt*4+2] = *(const uint32_t*)(q1 + kt * 16 + 8);
            aQl[kt*4+3] = *(const uint32_t*)(q1 + 8 * DD + kt * 16 + 8);
        }
    }

    const int rowA = i0 + wid * 16 + lq;
    const int rowB = rowA + 8;
    const bool rvA = rowA < seqlen;
    const bool rvB = rowB < seqlen;

    float mA = -INFINITY, mB = -INFINITY, lA = 0.f, lB = 0.f;
    float acc[8][4];
    #pragma unroll
    for (int n = 0; n < 8; n++)
        #pragma unroll
        for (int q = 0; q < 4; q++) acc[n][q] = 0.f;

    float* lgA = out_logits + ((size_t)bh * SS + rowA) * SS;
    float* lgB = out_logits + ((size_t)bh * SS + rowB) * SS;

    for (int jt = 0; jt < NJT; jt++) {
        __syncthreads();
        // stage K and V^T tiles (hi/lo)
        {
            const __nv_bfloat16* kh = g_kh + bh_off + (size_t)jt * TJ * DD;
            const __nv_bfloat16* kl = g_kl + bh_off + (size_t)jt * TJ * DD;
            #pragma unroll
            for (int c = tid; c < 512; c += NTHREADS) {
                int r = c >> 3, co = (c & 7) * 8;
                *(uint4*)(sKh + r * 72 + co) = *(const uint4*)(kh + r * DD + co);
                *(uint4*)(sKl + r * 72 + co) = *(const uint4*)(kl + r * DD + co);
                size_t vsrc = ((size_t)bh * DD + r) * SS + jt * TJ + co;
                *(uint4*)(sVh + r * 72 + co) = *(const uint4*)(g_vth + vsrc);
                *(uint4*)(sVl + r * 72 + co) = *(const uint4*)(g_vtl + vsrc);
            }
        }
        __syncthreads();

        // ---- S = Q K^T (3-product bf16 split) ----
        float s[8][4];
        #pragma unroll
        for (int nt = 0; nt < 8; nt++) {
            #pragma unroll
            for (int q = 0; q < 4; q++) s[nt][q] = 0.f;
            #pragma unroll
            for (int kt = 0; kt < 4; kt++) {
                const __nv_bfloat16* kp = sKh + (nt * 8 + lq) * 72 + kt * 16 + 2 * lr;
                const __nv_bfloat16* kpl = sKl + (nt * 8 + lq) * 72 + kt * 16 + 2 * lr;
                uint32_t bh0 = *(const uint32_t*)kp;
                uint32_t bh1 = *(const uint32_t*)(kp + 8);
                uint32_t bl0 = *(const uint32_t*)kpl;
                uint32_t bl1 = *(const uint32_t*)(kpl + 8);
                mma_bf16(s[nt], aQh + kt * 4, bh0, bh1);
                mma_bf16(s[nt], aQl + kt * 4, bh0, bh1);
                mma_bf16(s[nt], aQh + kt * 4, bl0, bl1);
            }
        }

        // ---- scale + mask + stream logits ----
        const int jb = jt * TJ;
        #pragma unroll
        for (int nt = 0; nt < 8; nt++) {
            int col = jb + nt * 8 + 2 * lr;
            bool c0v = col < seqlen;
            bool c1v = (col + 1) < seqlen;
            float v0 = (rvA && c0v) ? s[nt][0] * 0.125f : -1e10f;
            float v1 = (rvA && c1v) ? s[nt][1] * 0.125f : -1e10f;
            float v2 = (rvB && c0v) ? s[nt][2] * 0.125f : -1e10f;
            float v3 = (rvB && c1v) ? s[nt][3] * 0.125f : -1e10f;
            *(float2*)(lgA + col) = make_float2(v0, v1);
            *(float2*)(lgB + col) = make_float2(v2, v3);
            s[nt][0] = v0; s[nt][1] = v1; s[nt][2] = v2; s[nt][3] = v3;
        }

        // ---- online softmax ----
        float tmA = -INFINITY, tmB = -INFINITY;
        #pragma unroll
        for (int nt = 0; nt < 8; nt++) {
            tmA = fmaxf(tmA, fmaxf(s[nt][0], s[nt][1]));
            tmB = fmaxf(tmB, fmaxf(s[nt][2], s[nt][3]));
        }
        tmA = fmaxf(tmA, __shfl_xor_sync(0xffffffffu, tmA, 1));
        tmA = fmaxf(tmA, __shfl_xor_sync(0xffffffffu, tmA, 2));
        tmB = fmaxf(tmB, __shfl_xor_sync(0xffffffffu, tmB, 1));
        tmB = fmaxf(tmB, __shfl_xor_sync(0xffffffffu, tmB, 2));

        float mnA = fmaxf(mA, tmA), mnB = fmaxf(mB, tmB);
        float fA = __expf(mA - mnA), fB = __expf(mB - mnB);
        mA = mnA; mB = mnB;

        float sumA = 0.f, sumB = 0.f;
        #pragma unroll
        for (int nt = 0; nt < 8; nt++) {
            s[nt][0] = __expf(s[nt][0] - mnA);
            s[nt][1] = __expf(s[nt][1] - mnA);
            s[nt][2] = __expf(s[nt][2] - mnB);
            s[nt][3] = __expf(s[nt][3] - mnB);
            sumA += s[nt][0] + s[nt][1];
            sumB += s[nt][2] + s[nt][3];
        }
        sumA += __shfl_xor_sync(0xffffffffu, sumA, 1);
        sumA += __shfl_xor_sync(0xffffffffu, sumA, 2);
        sumB += __shfl_xor_sync(0xffffffffu, sumB, 1);
        sumB += __shfl_xor_sync(0xffffffffu, sumB, 2);
        lA = lA * fA + sumA;
        lB = lB * fB + sumB;

        #pragma unroll
        for (int nt = 0; nt < 8; nt++) {
            acc[nt][0] *= fA; acc[nt][1] *= fA;
            acc[nt][2] *= fB; acc[nt][3] *= fB;
        }

        // ---- pack P into hi/lo a-frags (reuse S c-frag layout) ----
        uint32_t aPh[16], aPl[16];
        #pragma unroll
        for (int kt = 0; kt < 4; kt++) {
            #pragma unroll
            for (int g = 0; g < 4; g++) {
                int nt = 2 * kt + (g >> 1);
                float p0 = s[nt][(g & 1) ? 2 : 0];
                float p1 = s[nt][(g & 1) ? 3 : 1];
                uint32_t hp = pack_bf16x2(p0, p1);
                float h0 = __uint_as_float(hp << 16);
                float h1 = __uint_as_float(hp & 0xffff0000u);
                aPh[kt * 4 + g] = hp;
                aPl[kt * 4 + g] = pack_bf16x2(p0 - h0, p1 - h1);
            }
        }

        // ---- X += P V (3-product split), V^T tiles give col-major B ----
        #pragma unroll
        for (int nt = 0; nt < 8; nt++) {
            #pragma unroll
            for (int kt = 0; kt < 4; kt++) {
                const __nv_bfloat16* vp = sVh + (nt * 8 + lq) * 72 + kt * 16 + 2 * lr;
                const __nv_bfloat16* vpl = sVl + (nt * 8 + lq) * 72 + kt * 16 + 2 * lr;
                uint32_t bh0 = *(const uint32_t*)vp;
                uint32_t bh1 = *(const uint32_t*)(vp + 8);
                uint32_t bl0 = *(const uint32_t*)vpl;
                uint32_t bl1 = *(const uint32_t*)(vpl + 8);
                mma_bf16(acc[nt], aPh + kt * 4, bh0, bh1);
                mma_bf16(acc[nt], aPl + kt * 4, bh0, bh1);
                mma_bf16(acc[nt], aPh + kt * 4, bl0, bl1);
            }
        }
    }

    // ---- epilogue ----
    const float liA = 1.f / lA, liB = 1.f / lB;
    float* xA = out_x + ((size_t)bh * SS + rowA) * DD;
    float* xB = out_x + ((size_t)bh * SS + rowB) * DD;
    #pragma unroll
    for (int nt = 0; nt < 8; nt++) {
        int col = nt * 8 + 2 * lr;
        *(float2*)(xA + col) = make_float2(acc[nt][0] * liA, acc[nt][1] * liA);
        *(float2*)(xB + col) = make_float2(acc[nt][2] * liB, acc[nt][3] * liB);
    }
}

extern "C" void kernel_launch(void* const* d_in, const int* in_sizes, int n_in,
                              void* d_out, int out_size) {
    const float* qkv     = (const float*)d_in[0];
    const float* cosb    = (const float*)d_in[1];
    const float* sinb    = (const float*)d_in[2];
    const int*   seqlens = (const int*)d_in[3];

    float* out        = (float*)d_out;
    float* out_x      = out;                                 // [B,H,S,D]
    float* out_logits = out + (size_t)BB * HH * SS * DD;     // [B,H,S,S]

    const int total_qk = BB * SS * 2 * HH * 32;
    rotary_qk_kernel<<<(total_qk + 255) / 256, 256>>>(qkv, cosb, sinb);
    vtrans_kernel<<<dim3(SS / 64, BH), NTHREADS>>>(qkv, cosb, sinb);
    attn_kernel<<<dim3(SS / TI, BH), NTHREADS>>>(seqlens, out_x, out_logits);
}

// round 4
// speedup vs baseline: 3.1507x; 1.3607x over previous
#include <cuda_runtime.h>
#include <cuda_bf16.h>
#include <math.h>
#include <stdint.h>

#define BB 2
#define SS 2048
#define HH 12
#define DD 64
#define BH (BB*HH)

#define TI 128
#define TJ 64
#define NJT (SS/TJ)
#define NTHREADS 256

#define NELEM (BB*HH*SS*DD)
// rotated bf16 hi/lo operands
__device__ __nv_bfloat16 g_qh[NELEM], g_ql[NELEM];   // [bh][s][d]
__device__ __nv_bfloat16 g_kh[NELEM], g_kl[NELEM];   // [bh][s][d]
__device__ __nv_bfloat16 g_vth[NELEM], g_vtl[NELEM]; // [bh][d][s] (transposed)

// smem tile layout: padded rows of 72 bf16 (144 B); 64 rows = 9216 B per array
#define ROWB 144
#define OKH 0
#define OKL 9216
#define OVH 18432
#define OVL 27648
#define BUF_BYTES 36864
#define SMEM_DYN (2 * BUF_BYTES)

// ---------------------------------------------------------------------------
__device__ __forceinline__ void mma_bf16(float (&c)[4], const uint32_t* a,
                                         uint32_t b0, uint32_t b1) {
    asm volatile(
        "mma.sync.aligned.m16n8k16.row.col.f32.bf16.bf16.f32 "
        "{%0,%1,%2,%3}, {%4,%5,%6,%7}, {%8,%9}, {%0,%1,%2,%3};\n"
        : "+f"(c[0]), "+f"(c[1]), "+f"(c[2]), "+f"(c[3])
        : "r"(a[0]), "r"(a[1]), "r"(a[2]), "r"(a[3]), "r"(b0), "r"(b1));
}

#define LDSM4(r0, r1, r2, r3, addr) \
    asm volatile("ldmatrix.sync.aligned.m8n8.x4.shared.b16 {%0,%1,%2,%3}, [%4];" \
        : "=r"(r0), "=r"(r1), "=r"(r2), "=r"(r3) : "r"(addr))

#define CP16(dst, src) \
    asm volatile("cp.async.cg.shared.global [%0], [%1], 16;" \
        :: "r"(dst), "l"(src) : "memory")
#define CP_COMMIT() asm volatile("cp.async.commit_group;" ::: "memory")
#define CP_WAIT(n)  asm volatile("cp.async.wait_group %0;" :: "n"(n) : "memory")

__device__ __forceinline__ uint32_t smem_u32(const void* p) {
    uint32_t a;
    asm("{ .reg .u64 t; cvta.to.shared.u64 t, %1; cvt.u32.u64 %0, t; }" : "=r"(a) : "l"(p));
    return a;
}

__device__ __forceinline__ uint32_t pack_bf16x2(float lo, float hi) {
    __nv_bfloat162 t = __floats2bfloat162_rn(lo, hi);
    return *(uint32_t*)&t;
}

// ---------------------------------------------------------------------------
// rotary for q,k -> bf16 hi/lo in [bh][s][d]
// ---------------------------------------------------------------------------
__global__ void rotary_qk_kernel(const float* __restrict__ qkv,
                                 const float* __restrict__ cosb,
                                 const float* __restrict__ sinb) {
    int idx = blockIdx.x * blockDim.x + threadIdx.x;
    const int total = BB * SS * 2 * HH * 32;
    if (idx >= total) return;
    int d2 = idx & 31; int rest = idx >> 5;
    int h = rest % HH; rest /= HH;
    int t = rest & 1;  rest >>= 1;
    int s = rest % SS; int b = rest / SS;

    size_t qoff = ((((size_t)b * SS + s) * 3 + t) * HH + h) * DD + d2;
    float x1 = qkv[qoff];
    float x2 = qkv[qoff + 32];
    int coff = (s * 3 + t) * DD + d2;
    float c = cosb[coff], sn = sinb[coff];
    float o1 = x1 * c - x2 * sn;
    float o2 = x2 * c + x1 * sn;

    __nv_bfloat16 h1 = __float2bfloat16_rn(o1);
    __nv_bfloat16 l1 = __float2bfloat16_rn(o1 - __bfloat162float(h1));
    __nv_bfloat16 h2 = __float2bfloat16_rn(o2);
    __nv_bfloat16 l2 = __float2bfloat16_rn(o2 - __bfloat162float(h2));

    __nv_bfloat16* dh = (t == 0) ? g_qh : g_kh;
    __nv_bfloat16* dl = (t == 0) ? g_ql : g_kl;
    size_t doff = (((size_t)b * HH + h) * SS + s) * DD + d2;
    dh[doff] = h1; dh[doff + 32] = h2;
    dl[doff] = l1; dl[doff + 32] = l2;
}

// ---------------------------------------------------------------------------
// v: rotary identity slice + transpose -> [bh][d][s] bf16 hi/lo
// ---------------------------------------------------------------------------
__global__ void vtrans_kernel(const float* __restrict__ qkv) {
    __shared__ __nv_bfloat16 sTh[64 * 72];
    __shared__ __nv_bfloat16 sTl[64 * 72];
    const int bh = blockIdx.y;
    const int b = bh / HH, h = bh % HH;
    const int s0 = blockIdx.x * 64;
    const int tid = threadIdx.x;
    const int sl = tid >> 2;
    const int d2b = (tid & 3) * 8;
    const int s = s0 + sl;

    const float* base = qkv + (((size_t)(b * SS + s) * 3 + 2) * HH + h) * DD;
    #pragma unroll
    for (int i = 0; i < 8; i++) {
        int d = d2b + i;
        float o1 = base[d], o2 = base[d + 32];
        __nv_bfloat16 h1 = __float2bfloat16_rn(o1);
        __nv_bfloat16 l1 = __float2bfloat16_rn(o1 - __bfloat162float(h1));
        __nv_bfloat16 h2 = __float2bfloat16_rn(o2);
        __nv_bfloat16 l2 = __float2bfloat16_rn(o2 - __bfloat162float(h2));
        sTh[d * 72 + sl] = h1; sTh[(d + 32) * 72 + sl] = h2;
        sTl[d * 72 + sl] = l1; sTl[(d + 32) * 72 + sl] = l2;
    }
    __syncthreads();
    #pragma unroll
    for (int c = tid; c < 512; c += NTHREADS) {
        int r = c >> 3, co = (c & 7) * 8;
        size_t dst = ((size_t)bh * DD + r) * SS + s0 + co;
        *(uint4*)(g_vth + dst) = *(const uint4*)(sTh + r * 72 + co);
        *(uint4*)(g_vtl + dst) = *(const uint4*)(sTl + r * 72 + co);
    }
}

// ---------------------------------------------------------------------------
// single-pass flash attention: mma.sync bf16 hi/lo split + ldmatrix + cp.async
// grid (SS/TI, BH), 256 threads (8 warps x 16 rows)
// ---------------------------------------------------------------------------
__global__ void __launch_bounds__(NTHREADS, 1)
attn_kernel(const int* __restrict__ seqlens,
            float* __restrict__ out_x,
            float* __restrict__ out_logits) {
    extern __shared__ char smem[];
    const uint32_t sb = smem_u32(smem);

    const int tid = threadIdx.x;
    const int wid = tid >> 5;
    const int lane = tid & 31;
    const int lq = lane >> 2;
    const int lr = lane & 3;

    const int bh = blockIdx.y;
    const int b = bh / HH;
    const int i0 = blockIdx.x * TI;
    const int seqlen = seqlens[b];
    const size_t bh_off = (size_t)bh * SS * DD;
    const size_t v_off = (size_t)bh * DD * SS;

    // per-lane ldmatrix offset within a tile: row (lane&7), matrix (lane>>3)
    const uint32_t lmo = (uint32_t)(lane & 7) * ROWB + (uint32_t)((lane >> 3) & 3) * 16;

    // persistent Q fragments (hi/lo)
    uint32_t aQh[16], aQl[16];
    {
        const __nv_bfloat16* q0 = g_qh + bh_off + (size_t)(i0 + wid * 16 + lq) * DD + 2 * lr;
        const __nv_bfloat16* q1 = g_ql + bh_off + (size_t)(i0 + wid * 16 + lq) * DD + 2 * lr;
        #pragma unroll
        for (int kt = 0; kt < 4; kt++) {
            aQh[kt*4+0] = *(const uint32_t*)(q0 + kt * 16);
            aQh[kt*4+1] = *(const uint32_t*)(q0 + 8 * DD + kt * 16);
            aQh[kt*4+2] = *(const uint32_t*)(q0 + kt * 16 + 8);
            aQh[kt*4+3] = *(const uint32_t*)(q0 + 8 * DD + kt * 16 + 8);
            aQl[kt*4+0] = *(const uint32_t*)(q1 + kt * 16);
            aQl[kt*4+1] = *(const uint32_t*)(q1 + 8 * DD + kt * 16);
            aQl[kt*4+2] = *(const uint32_t*)(q1 + kt * 16 + 8);
            aQl[kt*4+3] = *(const uint32_t*)(q1 + 8 * DD + kt * 16 + 8);
        }
    }

    const int rowA = i0 + wid * 16 + lq;
    const int rowB = rowA + 8;
    const bool rvA = rowA < seqlen;
    const bool rvB = rowB < seqlen;

    float mA = -INFINITY, mB = -INFINITY, lA = 0.f, lB = 0.f;
    float acc[8][4];
    #pragma unroll
    for (int n = 0; n < 8; n++)
        #pragma unroll
        for (int q = 0; q < 4; q++) acc[n][q] = 0.f;

    float* lgA = out_logits + ((size_t)bh * SS + rowA) * SS;
    float* lgB = out_logits + ((size_t)bh * SS + rowB) * SS;

    // ---- prefetch issue helper (8 cp.async per thread per tile) ----
    #define ISSUE_PREFETCH(JT, BUF) do { \
        uint32_t bba = sb + (BUF) * BUF_BYTES; \
        const __nv_bfloat16* _kh = g_kh + bh_off + (size_t)(JT) * TJ * DD; \
        const __nv_bfloat16* _kl = g_kl + bh_off + (size_t)(JT) * TJ * DD; \
        const __nv_bfloat16* _vh = g_vth + v_off + (size_t)(JT) * TJ; \
        const __nv_bfloat16* _vl = g_vtl + v_off + (size_t)(JT) * TJ; \
        _Pragma("unroll") \
        for (int c = tid; c < 512; c += NTHREADS) { \
            int r = c >> 3, co = (c & 7) * 8; \
            uint32_t dof = (uint32_t)r * ROWB + co * 2; \
            CP16(bba + OKH + dof, _kh + r * DD + co); \
            CP16(bba + OKL + dof, _kl + r * DD + co); \
            CP16(bba + OVH + dof, _vh + (size_t)r * SS + co); \
            CP16(bba + OVL + dof, _vl + (size_t)r * SS + co); \
        } \
        CP_COMMIT(); \
    } while (0)

    ISSUE_PREFETCH(0, 0);

    for (int jt = 0; jt < NJT; jt++) {
        if (jt + 1 < NJT) {
            ISSUE_PREFETCH(jt + 1, (jt + 1) & 1);
            CP_WAIT(1);
        } else {
            CP_WAIT(0);
        }
        __syncthreads();

        const uint32_t bba = sb + (jt & 1) * BUF_BYTES;
        const uint32_t uKh = bba + OKH, uKl = bba + OKL;
        const uint32_t uVh = bba + OVH, uVl = bba + OVL;

        // ---- S = Q K^T (3-product bf16 split) ----
        float s[8][4];
        #pragma unroll
        for (int nt = 0; nt < 8; nt++) {
            #pragma unroll
            for (int q = 0; q < 4; q++) s[nt][q] = 0.f;
            uint32_t kb[8], lb[8];
            uint32_t a0 = uKh + nt * (8 * ROWB) + lmo;
            uint32_t a1 = uKl + nt * (8 * ROWB) + lmo;
            LDSM4(kb[0], kb[1], kb[2], kb[3], a0);
            LDSM4(kb[4], kb[5], kb[6], kb[7], a0 + 64);
            LDSM4(lb[0], lb[1], lb[2], lb[3], a1);
            LDSM4(lb[4], lb[5], lb[6], lb[7], a1 + 64);
            #pragma unroll
            for (int kt = 0; kt < 4; kt++) {
                mma_bf16(s[nt], aQh + kt * 4, kb[2*kt], kb[2*kt+1]);
                mma_bf16(s[nt], aQl + kt * 4, kb[2*kt], kb[2*kt+1]);
                mma_bf16(s[nt], aQh + kt * 4, lb[2*kt], lb[2*kt+1]);
            }
        }

        // ---- scale + mask + stream logits ----
        const int jb = jt * TJ;
        #pragma unroll
        for (int nt = 0; nt < 8; nt++) {
            int col = jb + nt * 8 + 2 * lr;
            bool c0v = col < seqlen;
            bool c1v = (col + 1) < seqlen;
            float v0 = (rvA && c0v) ? s[nt][0] * 0.125f : -1e10f;
            float v1 = (rvA && c1v) ? s[nt][1] * 0.125f : -1e10f;
            float v2 = (rvB && c0v) ? s[nt][2] * 0.125f : -1e10f;
            float v3 = (rvB && c1v) ? s[nt][3] * 0.125f : -1e10f;
            *(float2*)(lgA + col) = make_float2(v0, v1);
            *(float2*)(lgB + col) = make_float2(v2, v3);
            s[nt][0] = v0; s[nt][1] = v1; s[nt][2] = v2; s[nt][3] = v3;
        }

        // ---- online softmax ----
        float tmA = -INFINITY, tmB = -INFINITY;
        #pragma unroll
        for (int nt = 0; nt < 8; nt++) {
            tmA = fmaxf(tmA, fmaxf(s[nt][0], s[nt][1]));
            tmB = fmaxf(tmB, fmaxf(s[nt][2], s[nt][3]));
        }
        tmA = fmaxf(tmA, __shfl_xor_sync(0xffffffffu, tmA, 1));
        tmA = fmaxf(tmA, __shfl_xor_sync(0xffffffffu, tmA, 2));
        tmB = fmaxf(tmB, __shfl_xor_sync(0xffffffffu, tmB, 1));
        tmB = fmaxf(tmB, __shfl_xor_sync(0xffffffffu, tmB, 2));

        float mnA = fmaxf(mA, tmA), mnB = fmaxf(mB, tmB);
        float fA = __expf(mA - mnA), fB = __expf(mB - mnB);
        mA = mnA; mB = mnB;

        float sumA = 0.f, sumB = 0.f;
        #pragma unroll
        for (int nt = 0; nt < 8; nt++) {
            s[nt][0] = __expf(s[nt][0] - mnA);
            s[nt][1] = __expf(s[nt][1] - mnA);
            s[nt][2] = __expf(s[nt][2] - mnB);
            s[nt][3] = __expf(s[nt][3] - mnB);
            sumA += s[nt][0] + s[nt][1];
            sumB += s[nt][2] + s[nt][3];
        }
        sumA += __shfl_xor_sync(0xffffffffu, sumA, 1);
        sumA += __shfl_xor_sync(0xffffffffu, sumA, 2);
        sumB += __shfl_xor_sync(0xffffffffu, sumB, 1);
        sumB += __shfl_xor_sync(0xffffffffu, sumB, 2);
        lA = lA * fA + sumA;
        lB = lB * fB + sumB;

        #pragma unroll
        for (int nt = 0; nt < 8; nt++) {
            acc[nt][0] *= fA; acc[nt][1] *= fA;
            acc[nt][2] *= fB; acc[nt][3] *= fB;
        }

        // ---- pack P into hi/lo a-frags (reuse S c-frag layout) ----
        uint32_t aPh[16], aPl[16];
        #pragma unroll
        for (int kt = 0; kt < 4; kt++) {
            #pragma unroll
            for (int g = 0; g < 4; g++) {
                int nt = 2 * kt + (g >> 1);
                float p0 = s[nt][(g & 1) ? 2 : 0];
                float p1 = s[nt][(g & 1) ? 3 : 1];
                uint32_t hp = pack_bf16x2(p0, p1);
                float h0 = __uint_as_float(hp << 16);
                float h1 = __uint_as_float(hp & 0xffff0000u);
                aPh[kt * 4 + g] = hp;
                aPl[kt * 4 + g] = pack_bf16x2(p0 - h0, p1 - h1);
            }
        }

        // ---- X += P V (3-product split) ----
        #pragma unroll
        for (int nt = 0; nt < 8; nt++) {
            uint32_t vb[8], wb[8];
            uint32_t a0 = uVh + nt * (8 * ROWB) + lmo;
            uint32_t a1 = uVl + nt * (8 * ROWB) + lmo;
            LDSM4(vb[0], vb[1], vb[2], vb[3], a0);
            LDSM4(vb[4], vb[5], vb[6], vb[7], a0 + 64);
            LDSM4(wb[0], wb[1], wb[2], wb[3], a1);
            LDSM4(wb[4], wb[5], wb[6], wb[7], a1 + 64);
            #pragma unroll
            for (int kt = 0; kt < 4; kt++) {
                mma_bf16(acc[nt], aPh + kt * 4, vb[2*kt], vb[2*kt+1]);
                mma_bf16(acc[nt], aPl + kt * 4, vb[2*kt], vb[2*kt+1]);
                mma_bf16(acc[nt], aPh + kt * 4, wb[2*kt], wb[2*kt+1]);
            }
        }
        __syncthreads();
    }

    // ---- epilogue ----
    const float liA = 1.f / lA, liB = 1.f / lB;
    float* xA = out_x + ((size_t)bh * SS + rowA) * DD;
    float* xB = out_x + ((size_t)bh * SS + rowB) * DD;
    #pragma unroll
    for (int nt = 0; nt < 8; nt++) {
        int col = nt * 8 + 2 * lr;
        *(float2*)(xA + col) = make_float2(acc[nt][0] * liA, acc[nt][1] * liA);
        *(float2*)(xB + col) = make_float2(acc[nt][2] * liB, acc[nt][3] * liB);
    }
}

extern "C" void kernel_launch(void* const* d_in, const int* in_sizes, int n_in,
                              void* d_out, int out_size) {
    const float* qkv     = (const float*)d_in[0];
    const float* cosb    = (const float*)d_in[1];
    const float* sinb    = (const float*)d_in[2];
    const int*   seqlens = (const int*)d_in[3];

    float* out        = (float*)d_out;
    float* out_x      = out;                                 // [B,H,S,D]
    float* out_logits = out + (size_t)BB * HH * SS * DD;     // [B,H,S,S]

    const int total_qk = BB * SS * 2 * HH * 32;
    rotary_qk_kernel<<<(total_qk + 255) / 256, 256>>>(qkv, cosb, sinb);
    vtrans_kernel<<<dim3(SS / 64, BH), NTHREADS>>>(qkv);

    cudaFuncSetAttribute(attn_kernel,
                         cudaFuncAttributeMaxDynamicSharedMemorySize, SMEM_DYN);
    attn_kernel<<<dim3(SS / TI, BH), NTHREADS, SMEM_DYN>>>(seqlens, out_x, out_logits);
}

// round 5
// speedup vs baseline: 3.7929x; 1.2038x over previous
#include <cuda_runtime.h>
#include <cuda_bf16.h>
#include <cuda_fp16.h>
#include <math.h>
#include <stdint.h>

#define BB 2
#define SS 2048
#define HH 12
#define DD 64
#define BH (BB*HH)

#define TI 128
#define TJ 64
#define NJT (SS/TJ)
#define NTHREADS 256

#define NELEM (BB*HH*SS*DD)
// rotated bf16 hi/lo operands for q,k; fp16 for v^T
__device__ __nv_bfloat16 g_qh[NELEM], g_ql[NELEM];   // [bh][s][d]
__device__ __nv_bfloat16 g_kh[NELEM], g_kl[NELEM];   // [bh][s][d]
__device__ __half        g_vt[NELEM];                // [bh][d][s] (transposed)

// smem tile layout: padded rows of 72 elems (144 B); 64 rows = 9216 B per array
#define ROWB 144
#define OKH 0
#define OKL 9216
#define OVH 18432
#define BUF_BYTES 27648
#define SMEM_DYN (2 * BUF_BYTES)

// ---------------------------------------------------------------------------
__device__ __forceinline__ void mma_bf16(float (&c)[4], const uint32_t* a,
                                         uint32_t b0, uint32_t b1) {
    asm volatile(
        "mma.sync.aligned.m16n8k16.row.col.f32.bf16.bf16.f32 "
        "{%0,%1,%2,%3}, {%4,%5,%6,%7}, {%8,%9}, {%0,%1,%2,%3};\n"
        : "+f"(c[0]), "+f"(c[1]), "+f"(c[2]), "+f"(c[3])
        : "r"(a[0]), "r"(a[1]), "r"(a[2]), "r"(a[3]), "r"(b0), "r"(b1));
}
__device__ __forceinline__ void mma_fp16(float (&c)[4], const uint32_t* a,
                                         uint32_t b0, uint32_t b1) {
    asm volatile(
        "mma.sync.aligned.m16n8k16.row.col.f32.f16.f16.f32 "
        "{%0,%1,%2,%3}, {%4,%5,%6,%7}, {%8,%9}, {%0,%1,%2,%3};\n"
        : "+f"(c[0]), "+f"(c[1]), "+f"(c[2]), "+f"(c[3])
        : "r"(a[0]), "r"(a[1]), "r"(a[2]), "r"(a[3]), "r"(b0), "r"(b1));
}

#define LDSM4(r0, r1, r2, r3, addr) \
    asm volatile("ldmatrix.sync.aligned.m8n8.x4.shared.b16 {%0,%1,%2,%3}, [%4];" \
        : "=r"(r0), "=r"(r1), "=r"(r2), "=r"(r3) : "r"(addr))

#define CP16(dst, src) \
    asm volatile("cp.async.cg.shared.global [%0], [%1], 16;" \
        :: "r"(dst), "l"(src) : "memory")
#define CP_COMMIT() asm volatile("cp.async.commit_group;" ::: "memory")
#define CP_WAIT(n)  asm volatile("cp.async.wait_group %0;" :: "n"(n) : "memory")

__device__ __forceinline__ uint32_t smem_u32(const void* p) {
    uint32_t a;
    asm("{ .reg .u64 t; cvta.to.shared.u64 t, %1; cvt.u32.u64 %0, t; }" : "=r"(a) : "l"(p));
    return a;
}

__device__ __forceinline__ uint32_t pack_bf16x2(float lo, float hi) {
    __nv_bfloat162 t = __floats2bfloat162_rn(lo, hi);
    return *(uint32_t*)&t;
}
__device__ __forceinline__ uint32_t pack_half2(float lo, float hi) {
    __half2 t = __floats2half2_rn(lo, hi);
    return *(uint32_t*)&t;
}

// ---------------------------------------------------------------------------
// rotary for q,k -> bf16 hi/lo in [bh][s][d]
// ---------------------------------------------------------------------------
__global__ void rotary_qk_kernel(const float* __restrict__ qkv,
                                 const float* __restrict__ cosb,
                                 const float* __restrict__ sinb) {
    int idx = blockIdx.x * blockDim.x + threadIdx.x;
    const int total = BB * SS * 2 * HH * 32;
    if (idx >= total) return;
    int d2 = idx & 31; int rest = idx >> 5;
    int h = rest % HH; rest /= HH;
    int t = rest & 1;  rest >>= 1;
    int s = rest % SS; int b = rest / SS;

    size_t qoff = ((((size_t)b * SS + s) * 3 + t) * HH + h) * DD + d2;
    float x1 = qkv[qoff];
    float x2 = qkv[qoff + 32];
    int coff = (s * 3 + t) * DD + d2;
    float c = cosb[coff], sn = sinb[coff];
    float o1 = x1 * c - x2 * sn;
    float o2 = x2 * c + x1 * sn;

    __nv_bfloat16 h1 = __float2bfloat16_rn(o1);
    __nv_bfloat16 l1 = __float2bfloat16_rn(o1 - __bfloat162float(h1));
    __nv_bfloat16 h2 = __float2bfloat16_rn(o2);
    __nv_bfloat16 l2 = __float2bfloat16_rn(o2 - __bfloat162float(h2));

    __nv_bfloat16* dh = (t == 0) ? g_qh : g_kh;
    __nv_bfloat16* dl = (t == 0) ? g_ql : g_kl;
    size_t doff = (((size_t)b * HH + h) * SS + s) * DD + d2;
    dh[doff] = h1; dh[doff + 32] = h2;
    dl[doff] = l1; dl[doff + 32] = l2;
}

// ---------------------------------------------------------------------------
// v: identity rotary slice + transpose -> [bh][d][s] fp16
// ---------------------------------------------------------------------------
__global__ void vtrans_kernel(const float* __restrict__ qkv) {
    __shared__ __half sT[64 * 72];
    const int bh = blockIdx.y;
    const int b = bh / HH, h = bh % HH;
    const int s0 = blockIdx.x * 64;
    const int tid = threadIdx.x;
    const int sl = tid >> 2;
    const int d2b = (tid & 3) * 8;
    const int s = s0 + sl;

    const float* base = qkv + (((size_t)(b * SS + s) * 3 + 2) * HH + h) * DD;
    #pragma unroll
    for (int i = 0; i < 8; i++) {
        int d = d2b + i;
        sT[d * 72 + sl]        = __float2half_rn(base[d]);
        sT[(d + 32) * 72 + sl] = __float2half_rn(base[d + 32]);
    }
    __syncthreads();
    #pragma unroll
    for (int c = tid; c < 512; c += NTHREADS) {
        int r = c >> 3, co = (c & 7) * 8;
        size_t dst = ((size_t)bh * DD + r) * SS + s0 + co;
        *(uint4*)(g_vt + dst) = *(const uint4*)(sT + r * 72 + co);
    }
}

// ---------------------------------------------------------------------------
// single-pass flash attention: bf16 3-product QK, fp16 1-product PV
// grid (SS/TI, BH), 256 threads (8 warps x 16 rows)
// ---------------------------------------------------------------------------
__global__ void __launch_bounds__(NTHREADS, 1)
attn_kernel(const int* __restrict__ seqlens,
            float* __restrict__ out_x,
            float* __restrict__ out_logits) {
    extern __shared__ char smem[];
    const uint32_t sb = smem_u32(smem);

    const int tid = threadIdx.x;
    const int wid = tid >> 5;
    const int lane = tid & 31;
    const int lq = lane >> 2;
    const int lr = lane & 3;

    const int bh = blockIdx.y;
    const int b = bh / HH;
    const int i0 = blockIdx.x * TI;
    const int seqlen = seqlens[b];
    const size_t bh_off = (size_t)bh * SS * DD;
    const size_t v_off = (size_t)bh * DD * SS;

    const uint32_t lmo = (uint32_t)(lane & 7) * ROWB + (uint32_t)((lane >> 3) & 3) * 16;

    // persistent Q fragments (hi/lo)
    uint32_t aQh[16], aQl[16];
    {
        const __nv_bfloat16* q0 = g_qh + bh_off + (size_t)(i0 + wid * 16 + lq) * DD + 2 * lr;
        const __nv_bfloat16* q1 = g_ql + bh_off + (size_t)(i0 + wid * 16 + lq) * DD + 2 * lr;
        #pragma unroll
        for (int kt = 0; kt < 4; kt++) {
            aQh[kt*4+0] = *(const uint32_t*)(q0 + kt * 16);
            aQh[kt*4+1] = *(const uint32_t*)(q0 + 8 * DD + kt * 16);
            aQh[kt*4+2] = *(const uint32_t*)(q0 + kt * 16 + 8);
            aQh[kt*4+3] = *(const uint32_t*)(q0 + 8 * DD + kt * 16 + 8);
            aQl[kt*4+0] = *(const uint32_t*)(q1 + kt * 16);
            aQl[kt*4+1] = *(const uint32_t*)(q1 + 8 * DD + kt * 16);
            aQl[kt*4+2] = *(const uint32_t*)(q1 + kt * 16 + 8);
            aQl[kt*4+3] = *(const uint32_t*)(q1 + 8 * DD + kt * 16 + 8);
        }
    }

    const int rowA = i0 + wid * 16 + lq;
    const int rowB = rowA + 8;
    const bool rvA = rowA < seqlen;
    const bool rvB = rowB < seqlen;

    float mA = -INFINITY, mB = -INFINITY, lA = 0.f, lB = 0.f;
    float acc[8][4];
    #pragma unroll
    for (int n = 0; n < 8; n++)
        #pragma unroll
        for (int q = 0; q < 4; q++) acc[n][q] = 0.f;

    float* lgA = out_logits + ((size_t)bh * SS + rowA) * SS;
    float* lgB = out_logits + ((size_t)bh * SS + rowB) * SS;

    // ---- prefetch: 6 cp.async per thread per tile (K hi/lo + V) ----
    #define ISSUE_PREFETCH(JT, BUF) do { \
        uint32_t bba = sb + (BUF) * BUF_BYTES; \
        const __nv_bfloat16* _kh = g_kh + bh_off + (size_t)(JT) * TJ * DD; \
        const __nv_bfloat16* _kl = g_kl + bh_off + (size_t)(JT) * TJ * DD; \
        const __half* _v = g_vt + v_off + (size_t)(JT) * TJ; \
        _Pragma("unroll") \
        for (int c = tid; c < 512; c += NTHREADS) { \
            int r = c >> 3, co = (c & 7) * 8; \
            uint32_t dof = (uint32_t)r * ROWB + co * 2; \
            CP16(bba + OKH + dof, _kh + r * DD + co); \
            CP16(bba + OKL + dof, _kl + r * DD + co); \
            CP16(bba + OVH + dof, _v + (size_t)r * SS + co); \
        } \
        CP_COMMIT(); \
    } while (0)

    ISSUE_PREFETCH(0, 0);

    for (int jt = 0; jt < NJT; jt++) {
        if (jt + 1 < NJT) {
            ISSUE_PREFETCH(jt + 1, (jt + 1) & 1);
            CP_WAIT(1);
        } else {
            CP_WAIT(0);
        }
        __syncthreads();

        const uint32_t bba = sb + (jt & 1) * BUF_BYTES;
        const uint32_t uKh = bba + OKH, uKl = bba + OKL, uVh = bba + OVH;

        // ---- S = Q K^T (3-product bf16 split) ----
        float s[8][4];
        #pragma unroll
        for (int nt = 0; nt < 8; nt++) {
            #pragma unroll
            for (int q = 0; q < 4; q++) s[nt][q] = 0.f;
            uint32_t kb[8], lb[8];
            uint32_t a0 = uKh + nt * (8 * ROWB) + lmo;
            uint32_t a1 = uKl + nt * (8 * ROWB) + lmo;
            LDSM4(kb[0], kb[1], kb[2], kb[3], a0);
            LDSM4(kb[4], kb[5], kb[6], kb[7], a0 + 64);
            LDSM4(lb[0], lb[1], lb[2], lb[3], a1);
            LDSM4(lb[4], lb[5], lb[6], lb[7], a1 + 64);
            #pragma unroll
            for (int kt = 0; kt < 4; kt++) {
                mma_bf16(s[nt], aQh + kt * 4, kb[2*kt], kb[2*kt+1]);
                mma_bf16(s[nt], aQl + kt * 4, kb[2*kt], kb[2*kt+1]);
                mma_bf16(s[nt], aQh + kt * 4, lb[2*kt], lb[2*kt+1]);
            }
        }

        // ---- scale + mask + stream logits ----
        const int jb = jt * TJ;
        #pragma unroll
        for (int nt = 0; nt < 8; nt++) {
            int col = jb + nt * 8 + 2 * lr;
            bool c0v = col < seqlen;
            bool c1v = (col + 1) < seqlen;
            float v0 = (rvA && c0v) ? s[nt][0] * 0.125f : -1e10f;
            float v1 = (rvA && c1v) ? s[nt][1] * 0.125f : -1e10f;
            float v2 = (rvB && c0v) ? s[nt][2] * 0.125f : -1e10f;
            float v3 = (rvB && c1v) ? s[nt][3] * 0.125f : -1e10f;
            *(float2*)(lgA + col) = make_float2(v0, v1);
            *(float2*)(lgB + col) = make_float2(v2, v3);
            s[nt][0] = v0; s[nt][1] = v1; s[nt][2] = v2; s[nt][3] = v3;
        }

        // ---- online softmax ----
        float tmA = -INFINITY, tmB = -INFINITY;
        #pragma unroll
        for (int nt = 0; nt < 8; nt++) {
            tmA = fmaxf(tmA, fmaxf(s[nt][0], s[nt][1]));
            tmB = fmaxf(tmB, fmaxf(s[nt][2], s[nt][3]));
        }
        tmA = fmaxf(tmA, __shfl_xor_sync(0xffffffffu, tmA, 1));
        tmA = fmaxf(tmA, __shfl_xor_sync(0xffffffffu, tmA, 2));
        tmB = fmaxf(tmB, __shfl_xor_sync(0xffffffffu, tmB, 1));
        tmB = fmaxf(tmB, __shfl_xor_sync(0xffffffffu, tmB, 2));

        float mnA = fmaxf(mA, tmA), mnB = fmaxf(mB, tmB);
        float fA = __expf(mA - mnA), fB = __expf(mB - mnB);
        mA = mnA; mB = mnB;

        float sumA = 0.f, sumB = 0.f;
        #pragma unroll
        for (int nt = 0; nt < 8; nt++) {
            s[nt][0] = __expf(s[nt][0] - mnA);
            s[nt][1] = __expf(s[nt][1] - mnA);
            s[nt][2] = __expf(s[nt][2] - mnB);
            s[nt][3] = __expf(s[nt][3] - mnB);
            sumA += s[nt][0] + s[nt][1];
            sumB += s[nt][2] + s[nt][3];
        }
        sumA += __shfl_xor_sync(0xffffffffu, sumA, 1);
        sumA += __shfl_xor_sync(0xffffffffu, sumA, 2);
        sumB += __shfl_xor_sync(0xffffffffu, sumB, 1);
        sumB += __shfl_xor_sync(0xffffffffu, sumB, 2);
        lA = lA * fA + sumA;
        lB = lB * fB + sumB;

        #pragma unroll
        for (int nt = 0; nt < 8; nt++) {
            acc[nt][0] *= fA; acc[nt][1] *= fA;
            acc[nt][2] *= fB; acc[nt][3] *= fB;
        }

        // ---- pack P into fp16 a-frags (reuse S c-frag layout) ----
        uint32_t aP[16];
        #pragma unroll
        for (int kt = 0; kt < 4; kt++) {
            #pragma unroll
            for (int g = 0; g < 4; g++) {
                int nt = 2 * kt + (g >> 1);
                float p0 = s[nt][(g & 1) ? 2 : 0];
                float p1 = s[nt][(g & 1) ? 3 : 1];
                aP[kt * 4 + g] = pack_half2(p0, p1);
            }
        }

        // ---- X += P V (single fp16 product) ----
        #pragma unroll
        for (int nt = 0; nt < 8; nt++) {
            uint32_t vb[8];
            uint32_t a0 = uVh + nt * (8 * ROWB) + lmo;
            LDSM4(vb[0], vb[1], vb[2], vb[3], a0);
            LDSM4(vb[4], vb[5], vb[6], vb[7], a0 + 64);
            #pragma unroll
            for (int kt = 0; kt < 4; kt++)
                mma_fp16(acc[nt], aP + kt * 4, vb[2*kt], vb[2*kt+1]);
        }
        __syncthreads();
    }

    // ---- epilogue ----
    const float liA = 1.f / lA, liB = 1.f / lB;
    float* xA = out_x + ((size_t)bh * SS + rowA) * DD;
    float* xB = out_x + ((size_t)bh * SS + rowB) * DD;
    #pragma unroll
    for (int nt = 0; nt < 8; nt++) {
        int col = nt * 8 + 2 * lr;
        *(float2*)(xA + col) = make_float2(acc[nt][0] * liA, acc[nt][1] * liA);
        *(float2*)(xB + col) = make_float2(acc[nt][2] * liB, acc[nt][3] * liB);
    }
}

extern "C" void kernel_launch(void* const* d_in, const int* in_sizes, int n_in,
                              void* d_out, int out_size) {
    const float* qkv     = (const float*)d_in[0];
    const float* cosb    = (const float*)d_in[1];
    const float* sinb    = (const float*)d_in[2];
    const int*   seqlens = (const int*)d_in[3];

    float* out        = (float*)d_out;
    float* out_x      = out;                                 // [B,H,S,D]
    float* out_logits = out + (size_t)BB * HH * SS * DD;     // [B,H,S,S]

    const int total_qk = BB * SS * 2 * HH * 32;
    rotary_qk_kernel<<<(total_qk + 255) / 256, 256>>>(qkv, cosb, sinb);
    vtrans_kernel<<<dim3(SS / 64, BH), NTHREADS>>>(qkv);

    cudaFuncSetAttribute(attn_kernel,
                         cudaFuncAttributeMaxDynamicSharedMemorySize, SMEM_DYN);
    attn_kernel<<<dim3(SS / TI, BH), NTHREADS, SMEM_DYN>>>(seqlens, out_x, out_logits);
}